// round 1
// baseline (speedup 1.0000x reference)
#include <cuda_runtime.h>
#include <cstdint>

#define VOCAB   250002
#define BATCH   16
#define SEQ     2048
#define HDIM    1024
#define SM1     2047               // SEQ-1
#define MROWS   (BATCH * SM1)      // 32752
#define EPSN    1e-12f

typedef unsigned long long ull;

// ---------------- packed f32x2 helpers (Blackwell FFMA2) ----------------
static __device__ __forceinline__ ull pack2(float lo, float hi) {
    ull r;
    asm("mov.b64 %0, {%1, %2};" : "=l"(r) : "f"(lo), "f"(hi));
    return r;
}
static __device__ __forceinline__ void fma2(ull& d, ull a, ull b) {
    asm("fma.rn.f32x2 %0, %1, %2, %0;" : "+l"(d) : "l"(a), "l"(b));
}
static __device__ __forceinline__ float2 unpack2(ull v) {
    float2 f;
    asm("mov.b64 {%0, %1}, %2;" : "=f"(f.x), "=f"(f.y) : "l"(v));
    return f;
}

// ---------------- colbert GEMM: C[m,n] = A[mrow(m),:] . W[:,n] + bias[n] ----------------
// A = hidden_state viewed as (B*S, H); output row m -> A row = m + m/2047 + 1
#define BM 128
#define BN 128
#define BK 16
#define TM 8
#define TN 8

__global__ __launch_bounds__(256)
void colbert_gemm(const float* __restrict__ A, const float* __restrict__ W,
                  const float* __restrict__ bias, float* __restrict__ C) {
    __shared__ float As[BK][BM + 4];   // padded, row stride 132 floats (16B aligned)
    __shared__ float Bs[BK][BN];

    const int t  = threadIdx.x;
    const int bm = blockIdx.y;
    const int bn = blockIdx.x;

    // ---- A tile load mapping: rows t/4 and t/4+64, cols (t%4)*4 ----
    const int lr = t >> 2;
    const int lc = (t & 3) << 2;
    const int m0 = bm * BM + lr;
    const int m1 = m0 + 64;
    const bool v0 = (m0 < MROWS);
    const bool v1 = (m1 < MROWS);
    const float* ap0 = A + (size_t)(v0 ? (m0 + m0 / SM1 + 1) : 0) * HDIM + lc;
    const float* ap1 = A + (size_t)(v1 ? (m1 + m1 / SM1 + 1) : 0) * HDIM + lc;

    // ---- B tile load mapping: rows t/32 and t/32+8, cols (t%32)*4 ----
    const int br = t >> 5;
    const int bc = (t & 31) << 2;
    const float* bbase = W + (size_t)bn * BN + bc;

    // ---- compute fragment mapping: warp = 8(tx) x 4(ty) ----
    const int lane = t & 31;
    const int w    = t >> 5;
    const int tx   = ((w & 1) << 3) + (lane & 7);   // 0..15
    const int ty   = ((w >> 1) << 2) + (lane >> 3); // 0..15

    ull acc[TM][TN / 2];
#pragma unroll
    for (int i = 0; i < TM; i++)
#pragma unroll
        for (int j = 0; j < TN / 2; j++) acc[i][j] = 0ull;

    const float4 zero4 = make_float4(0.f, 0.f, 0.f, 0.f);

    // prologue: load tile 0
    float4 ra0 = v0 ? *(const float4*)(ap0) : zero4;
    float4 ra1 = v1 ? *(const float4*)(ap1) : zero4;
    float4 rb0 = *(const float4*)(bbase + (size_t)(br)     * HDIM);
    float4 rb1 = *(const float4*)(bbase + (size_t)(br + 8) * HDIM);

    As[lc + 0][lr] = ra0.x; As[lc + 1][lr] = ra0.y; As[lc + 2][lr] = ra0.z; As[lc + 3][lr] = ra0.w;
    As[lc + 0][lr + 64] = ra1.x; As[lc + 1][lr + 64] = ra1.y; As[lc + 2][lr + 64] = ra1.z; As[lc + 3][lr + 64] = ra1.w;
    *(float4*)&Bs[br][bc]     = rb0;
    *(float4*)&Bs[br + 8][bc] = rb1;

    const int NIT = HDIM / BK;  // 64
    for (int it = 0; it < NIT; it++) {
        __syncthreads();
        const bool more = (it + 1 < NIT);
        if (more) {
            const int k0 = (it + 1) * BK;
            ra0 = v0 ? *(const float4*)(ap0 + k0) : zero4;
            ra1 = v1 ? *(const float4*)(ap1 + k0) : zero4;
            rb0 = *(const float4*)(bbase + (size_t)(k0 + br)     * HDIM);
            rb1 = *(const float4*)(bbase + (size_t)(k0 + br + 8) * HDIM);
        }
#pragma unroll
        for (int kk = 0; kk < BK; kk++) {
            const float4 av0 = *(const float4*)&As[kk][ty * TM];
            const float4 av1 = *(const float4*)&As[kk][ty * TM + 4];
            const ulonglong2 bq0 = *(const ulonglong2*)&Bs[kk][tx * TN];
            const ulonglong2 bq1 = *(const ulonglong2*)&Bs[kk][tx * TN + 4];
            const ull b2[4] = {bq0.x, bq0.y, bq1.x, bq1.y};
            const float a[8] = {av0.x, av0.y, av0.z, av0.w, av1.x, av1.y, av1.z, av1.w};
#pragma unroll
            for (int i = 0; i < TM; i++) {
                const ull a2 = pack2(a[i], a[i]);
#pragma unroll
                for (int j = 0; j < TN / 2; j++) fma2(acc[i][j], a2, b2[j]);
            }
        }
        __syncthreads();
        if (more) {
            As[lc + 0][lr] = ra0.x; As[lc + 1][lr] = ra0.y; As[lc + 2][lr] = ra0.z; As[lc + 3][lr] = ra0.w;
            As[lc + 0][lr + 64] = ra1.x; As[lc + 1][lr + 64] = ra1.y; As[lc + 2][lr + 64] = ra1.z; As[lc + 3][lr + 64] = ra1.w;
            *(float4*)&Bs[br][bc]     = rb0;
            *(float4*)&Bs[br + 8][bc] = rb1;
        }
    }

    // epilogue: add bias, store raw (pre-mask, pre-norm)
    const int nbase = bn * BN + tx * TN;
    float bvals[TN];
#pragma unroll
    for (int j = 0; j < TN; j++) bvals[j] = bias[nbase + j];
#pragma unroll
    for (int i = 0; i < TM; i++) {
        const int m = bm * BM + ty * TM + i;
        if (m >= MROWS) continue;
        float* crow = C + (size_t)m * HDIM + nbase;
#pragma unroll
        for (int j = 0; j < TN / 2; j++) {
            float2 v = unpack2(acc[i][j]);
            crow[2 * j]     = v.x + bvals[2 * j];
            crow[2 * j + 1] = v.y + bvals[2 * j + 1];
        }
    }
}

// ---------------- row-wise mask + L2 normalize (in place), colbert rows ----------------
__global__ __launch_bounds__(256)
void colbert_norm(float* __restrict__ C, const float* __restrict__ mask) {
    const int r = blockIdx.x;
    const int b = r / SM1;
    const int s = r - b * SM1 + 1;
    const float mk = mask[b * SEQ + s];
    float4* row = (float4*)(C + (size_t)r * HDIM);
    const int t = threadIdx.x;
    float4 v = row[t];
    v.x *= mk; v.y *= mk; v.z *= mk; v.w *= mk;
    float ss = v.x * v.x + v.y * v.y + v.z * v.z + v.w * v.w;
#pragma unroll
    for (int o = 16; o > 0; o >>= 1) ss += __shfl_xor_sync(0xFFFFFFFFu, ss, o);
    __shared__ float ws[8];
    __shared__ float sscale;
    if ((t & 31) == 0) ws[t >> 5] = ss;
    __syncthreads();
    if (t == 0) {
        float tot = 0.f;
#pragma unroll
        for (int i = 0; i < 8; i++) tot += ws[i];
        sscale = 1.f / fmaxf(sqrtf(tot), EPSN);
    }
    __syncthreads();
    const float sc = sscale;
    v.x *= sc; v.y *= sc; v.z *= sc; v.w *= sc;
    row[t] = v;
}

// ---------------- dense head: L2-normalize hidden[b, 0, :] ----------------
__global__ __launch_bounds__(256)
void dense_norm(const float* __restrict__ hs, float* __restrict__ o) {
    const int b = blockIdx.x;
    const int t = threadIdx.x;
    const float4* row = (const float4*)(hs + (size_t)b * SEQ * HDIM);
    float4 v = row[t];
    float ss = v.x * v.x + v.y * v.y + v.z * v.z + v.w * v.w;
#pragma unroll
    for (int o2 = 16; o2 > 0; o2 >>= 1) ss += __shfl_xor_sync(0xFFFFFFFFu, ss, o2);
    __shared__ float ws[8];
    __shared__ float sscale;
    if ((t & 31) == 0) ws[t >> 5] = ss;
    __syncthreads();
    if (t == 0) {
        float tot = 0.f;
#pragma unroll
        for (int i = 0; i < 8; i++) tot += ws[i];
        sscale = 1.f / fmaxf(sqrtf(tot), EPSN);
    }
    __syncthreads();
    const float sc = sscale;
    v.x *= sc; v.y *= sc; v.z *= sc; v.w *= sc;
    ((float4*)(o + (size_t)b * HDIM))[t] = v;
}

// ---------------- sparse head ----------------
__global__ __launch_bounds__(512)
void sparse_zero(float4* __restrict__ p) {
    const int n = (BATCH * VOCAB) / 4;  // 1000008, exact
    const float4 z = make_float4(0.f, 0.f, 0.f, 0.f);
    for (int i = blockIdx.x * blockDim.x + threadIdx.x; i < n; i += gridDim.x * blockDim.x)
        p[i] = z;
}

// one warp per token: dot(hidden[tok], sparse_W) -> relu -> atomicMax scatter
__global__ __launch_bounds__(256)
void sparse_scatter(const float* __restrict__ hs, const int* __restrict__ idw,
                    const float* __restrict__ sw, const float* __restrict__ sb,
                    float* __restrict__ sp) {
    __shared__ float wsh[HDIM];
    const int t = threadIdx.x;
    ((float4*)wsh)[t] = ((const float4*)sw)[t];
    __syncthreads();

    const int lane = t & 31;
    const int wp   = t >> 5;

    // int64-vs-int32 layout detection: int64 ids (< 2^31, >=0) have all-zero high words.
    const int odd = idw[2 * lane + 1];
    const bool is64 = __all_sync(0xFFFFFFFFu, odd == 0);

    const int tok = blockIdx.x * 8 + wp;            // [0, 32768)
    const float* row = hs + (size_t)tok * HDIM;
    float s = 0.f;
#pragma unroll
    for (int j = 0; j < 8; j++) {
        const float4 h  = *(const float4*)(row + lane * 4 + j * 128);
        const float4 ww = *(const float4*)(wsh + lane * 4 + j * 128);
        s += h.x * ww.x + h.y * ww.y + h.z * ww.z + h.w * ww.w;
    }
#pragma unroll
    for (int o = 16; o > 0; o >>= 1) s += __shfl_xor_sync(0xFFFFFFFFu, s, o);

    if (lane == 0) {
        const float val = s + sb[0];
        if (val > 0.f) {
            long long id = is64 ? ((const long long*)idw)[tok] : (long long)idw[tok];
            if (id >= 0 && id < VOCAB) {
                const int b = tok >> 11;  // tok / SEQ
                atomicMax((int*)&sp[(size_t)b * VOCAB + (int)id], __float_as_int(val));
            }
        }
    }
}

__global__ void zero_special(float* __restrict__ sp) {
    const int t = threadIdx.x;  // 64 threads
    const int ids[4] = {0, 2, 1, 3};
    const int b = t >> 2;
    if (b < BATCH) sp[(size_t)b * VOCAB + ids[t & 3]] = 0.f;
}

// ---------------- launch ----------------
extern "C" void kernel_launch(void* const* d_in, const int* in_sizes, int n_in,
                              void* d_out, int out_size) {
    const float* hs   = (const float*)d_in[0];  // (16, 2048, 1024) f32
    const float* mask = (const float*)d_in[1];  // (16, 2048) f32
    const int*   ids  = (const int*)d_in[2];    // (16, 2048) int32 or int64 (detected)
    const float* sW   = (const float*)d_in[3];  // (1024, 1)
    const float* sb   = (const float*)d_in[4];  // (1,)
    const float* cW   = (const float*)d_in[5];  // (1024, 1024)
    const float* cb   = (const float*)d_in[6];  // (1024,)

    float* out      = (float*)d_out;
    float* o_dense  = out;                                   // 16*1024
    float* o_sparse = out + (size_t)BATCH * HDIM;            // 16*250002
    float* o_col    = o_sparse + (size_t)BATCH * VOCAB;      // 16*2047*1024

    dense_norm<<<BATCH, 256>>>(hs, o_dense);
    sparse_zero<<<2048, 512>>>((float4*)o_sparse);
    sparse_scatter<<<(BATCH * SEQ) / 8, 256>>>(hs, ids, sW, sb, o_sparse);
    zero_special<<<1, 64>>>(o_sparse);

    dim3 grid(HDIM / BN, (MROWS + BM - 1) / BM);
    colbert_gemm<<<grid, 256>>>(hs, cW, cb, o_col);
    colbert_norm<<<MROWS, 256>>>(o_col, mask);
}

// round 10
// speedup vs baseline: 1.9620x; 1.9620x over previous
#include <cuda_runtime.h>
#include <cuda_bf16.h>
#include <cstdint>

#define VOCAB   250002
#define BATCH   16
#define SEQ     2048
#define HDIM    1024
#define SM1     2047               // SEQ-1
#define MROWS   (BATCH * SM1)      // 32752
#define EPSN    1e-12f

// ===================== small helpers =====================
static __device__ __forceinline__ uint32_t smem_u32(const void* p) {
    uint32_t a;
    asm("{ .reg .u64 t; cvta.to.shared.u64 t, %1; cvt.u32.u64 %0, t; }" : "=r"(a) : "l"(p));
    return a;
}
// pack two floats to bf16x2 (first arg -> low half)
static __device__ __forceinline__ unsigned bpack(float lo, float hi) {
    unsigned r;
    asm("cvt.rn.bf16x2.f32 %0, %1, %2;" : "=r"(r) : "f"(hi), "f"(lo));
    return r;
}

#define CP_ASYNC16(s, g) \
    asm volatile("cp.async.cg.shared.global [%0], [%1], 16;" :: "r"(s), "l"(g))
#define CP_COMMIT()  asm volatile("cp.async.commit_group;" ::: "memory")
#define CP_WAIT0()   asm volatile("cp.async.wait_group 0;" ::: "memory")

#define LDSM4(R, a) \
    asm volatile("ldmatrix.sync.aligned.m8n8.x4.shared.b16 {%0,%1,%2,%3}, [%4];" \
        : "=r"((R)[0]), "=r"((R)[1]), "=r"((R)[2]), "=r"((R)[3]) : "r"(a))

#define MMA16816(D, A, B0, B1) \
    asm volatile("mma.sync.aligned.m16n8k16.row.col.f32.bf16.bf16.f32 " \
        "{%0,%1,%2,%3}, {%4,%5,%6,%7}, {%8,%9}, {%0,%1,%2,%3};" \
        : "+f"((D)[0]), "+f"((D)[1]), "+f"((D)[2]), "+f"((D)[3]) \
        : "r"((A)[0]), "r"((A)[1]), "r"((A)[2]), "r"((A)[3]), "r"(B0), "r"(B1))

// ===================== W pre-transpose + hi/lo split =====================
__device__ __nv_bfloat16 g_Wt_hi[HDIM * HDIM];   // [N, K] K-contig
__device__ __nv_bfloat16 g_Wt_lo[HDIM * HDIM];

__global__ __launch_bounds__(256)
void prep_w(const float* __restrict__ W) {
    __shared__ float tile[32][33];
    const int tx = threadIdx.x, ty = threadIdx.y;     // (32, 8)
    const int n0 = blockIdx.x * 32, k0 = blockIdx.y * 32;
#pragma unroll
    for (int i = 0; i < 32; i += 8)
        tile[ty + i][tx] = W[(size_t)(k0 + ty + i) * HDIM + n0 + tx];
    __syncthreads();
#pragma unroll
    for (int i = 0; i < 32; i += 8) {
        const int n = n0 + ty + i, k = k0 + tx;
        float v = tile[tx][ty + i];
        __nv_bfloat16 h = __float2bfloat16_rn(v);
        float r = v - __bfloat162float(h);
        g_Wt_hi[(size_t)n * HDIM + k] = h;
        g_Wt_lo[(size_t)n * HDIM + k] = __float2bfloat16_rn(r);
    }
}

// ===================== colbert GEMM via mma.sync bf16 (3-term split) =====================
// C[m,n] = A[mrow(m),:] . W[:,n] + bias[n],  mrow(m) = m + m/2047 + 1
#define BM 128
#define BN 128
#define BKC 32                       // bf16 k per chunk
#define NC  (HDIM / BKC)             // 32 chunks
#define ROWB 80                      // padded smem row bytes (32 bf16 data + 16B pad)
#define PLANE (BM * ROWB)            // 10240 B
#define STAGE (4 * PLANE)            // Ah, Al, Bh, Bl
#define GEMM_SMEM (2 * STAGE)        // 81920 B

__global__ __launch_bounds__(256, 1)
void colbert_gemm_mma(const float* __restrict__ A, const float* __restrict__ bias,
                      float* __restrict__ C) {
    extern __shared__ char smem[];
    const uint32_t sb = smem_u32(smem);
    const int t = threadIdx.x, lane = t & 31, wid = t >> 5;
    const int m0 = blockIdx.y * BM;
    const int n0 = blockIdx.x * BN;

    // ---- load mappings (per thread): row r = t>>1, 32B half h = t&1 ----
    const int lr = t >> 1, lh = t & 1;
    const int am = m0 + lr;
    const int arow = (am < MROWS) ? (am + am / SM1 + 1) : 0;
    const float4* ap4 = (const float4*)(A + (size_t)arow * HDIM) + lh * 4;
    const __nv_bfloat16* gbh = g_Wt_hi + (size_t)(n0 + lr) * HDIM + lh * 16;
    const __nv_bfloat16* gbl = g_Wt_lo + (size_t)(n0 + lr) * HDIM + lh * 16;

    const uint32_t s_row = (uint32_t)lr * ROWB + (uint32_t)lh * 32;

    // ---- warp compute mapping: 4(m) x 2(n) warps; warp tile 32x64 ----
    const int wm = wid >> 1, wn = wid & 1;
    // ldmatrix thread-address row/col-byte (A-matrix ordering and B-matrix ordering)
    const uint32_t a_r  = (uint32_t)((lane & 7) + ((lane >> 3) & 1) * 8);
    const uint32_t a_kb = (uint32_t)((lane >> 4) * 16);
    const uint32_t b_r  = (uint32_t)((lane & 7) + ((lane >> 4) & 1) * 8);
    const uint32_t b_kb = (uint32_t)(((lane >> 3) & 1) * 16);

    float d[2][8][4];
#pragma unroll
    for (int i = 0; i < 2; i++)
#pragma unroll
        for (int j = 0; j < 8; j++)
#pragma unroll
            for (int q = 0; q < 4; q++) d[i][j][q] = 0.f;

    float4 av[4];
    // ---------------- prologue: fill stage 0 ----------------
#pragma unroll
    for (int j = 0; j < 4; j++) av[j] = ap4[j];
    {
        uint32_t sB = sb + 2 * PLANE + s_row;
        CP_ASYNC16(sB,              gbh);
        CP_ASYNC16(sB + 16,         gbh + 8);
        CP_ASYNC16(sB + PLANE,      gbl);
        CP_ASYNC16(sB + PLANE + 16, gbl + 8);
        CP_COMMIT();
    }
    {
        char* sAh = smem + s_row;
        char* sAl = sAh + PLANE;
        unsigned hh[8], ll[8];
#pragma unroll
        for (int j = 0; j < 4; j++) {
            unsigned h0 = bpack(av[j].x, av[j].y);
            unsigned h1 = bpack(av[j].z, av[j].w);
            float rx = av[j].x - __uint_as_float(h0 << 16);
            float ry = av[j].y - __uint_as_float(h0 & 0xFFFF0000u);
            float rz = av[j].z - __uint_as_float(h1 << 16);
            float rw = av[j].w - __uint_as_float(h1 & 0xFFFF0000u);
            hh[2 * j] = h0; hh[2 * j + 1] = h1;
            ll[2 * j] = bpack(rx, ry); ll[2 * j + 1] = bpack(rz, rw);
        }
        *(uint4*)(sAh)      = make_uint4(hh[0], hh[1], hh[2], hh[3]);
        *(uint4*)(sAh + 16) = make_uint4(hh[4], hh[5], hh[6], hh[7]);
        *(uint4*)(sAl)      = make_uint4(ll[0], ll[1], ll[2], ll[3]);
        *(uint4*)(sAl + 16) = make_uint4(ll[4], ll[5], ll[6], ll[7]);
    }

    // ---------------- main loop ----------------
    for (int c = 0; c < NC; c++) {
        const int s = c & 1;
        CP_WAIT0();
        __syncthreads();

        const bool more = (c + 1 < NC);
        if (more) {
#pragma unroll
            for (int j = 0; j < 4; j++) av[j] = ap4[(c + 1) * 8 + j];
            uint32_t sB = sb + (s ^ 1) * STAGE + 2 * PLANE + s_row;
            const __nv_bfloat16* gh = gbh + (c + 1) * BKC;
            const __nv_bfloat16* gl = gbl + (c + 1) * BKC;
            CP_ASYNC16(sB,              gh);
            CP_ASYNC16(sB + 16,         gh + 8);
            CP_ASYNC16(sB + PLANE,      gl);
            CP_ASYNC16(sB + PLANE + 16, gl + 8);
            CP_COMMIT();
        }

        // ---- MMA over stage s ----
        {
            const uint32_t st = sb + s * STAGE;
            const uint32_t aA = st + (uint32_t)(wm * 32) * ROWB + a_r * ROWB + a_kb;
            const uint32_t aB = st + 2 * PLANE + (uint32_t)(wn * 64) * ROWB + b_r * ROWB + b_kb;
#pragma unroll
            for (int k16 = 0; k16 < 2; k16++) {
                const uint32_t ko = (uint32_t)(k16 * 32);
                unsigned ah[2][4], al[2][4], bh[4][4], bl[4][4];
#pragma unroll
                for (int mt = 0; mt < 2; mt++) {
                    LDSM4(ah[mt], aA + (uint32_t)(mt * 16) * ROWB + ko);
                    LDSM4(al[mt], aA + (uint32_t)(mt * 16) * ROWB + ko + PLANE);
                }
#pragma unroll
                for (int p = 0; p < 4; p++) {
                    LDSM4(bh[p], aB + (uint32_t)(p * 16) * ROWB + ko);
                    LDSM4(bl[p], aB + (uint32_t)(p * 16) * ROWB + ko + PLANE);
                }
#pragma unroll
                for (int mt = 0; mt < 2; mt++)
#pragma unroll
                    for (int p = 0; p < 4; p++) {
                        MMA16816(d[mt][2 * p],     ah[mt], bh[p][0], bh[p][1]);
                        MMA16816(d[mt][2 * p + 1], ah[mt], bh[p][2], bh[p][3]);
                        MMA16816(d[mt][2 * p],     ah[mt], bl[p][0], bl[p][1]);
                        MMA16816(d[mt][2 * p + 1], ah[mt], bl[p][2], bl[p][3]);
                        MMA16816(d[mt][2 * p],     al[mt], bh[p][0], bh[p][1]);
                        MMA16816(d[mt][2 * p + 1], al[mt], bh[p][2], bh[p][3]);
                    }
            }
        }

        // ---- convert+store A for next chunk into stage s^1 ----
        if (more) {
            char* sAh = smem + (s ^ 1) * STAGE + s_row;
            char* sAl = sAh + PLANE;
            unsigned hh[8], ll[8];
#pragma unroll
            for (int j = 0; j < 4; j++) {
                unsigned h0 = bpack(av[j].x, av[j].y);
                unsigned h1 = bpack(av[j].z, av[j].w);
                float rx = av[j].x - __uint_as_float(h0 << 16);
                float ry = av[j].y - __uint_as_float(h0 & 0xFFFF0000u);
                float rz = av[j].z - __uint_as_float(h1 << 16);
                float rw = av[j].w - __uint_as_float(h1 & 0xFFFF0000u);
                hh[2 * j] = h0; hh[2 * j + 1] = h1;
                ll[2 * j] = bpack(rx, ry); ll[2 * j + 1] = bpack(rz, rw);
            }
            *(uint4*)(sAh)      = make_uint4(hh[0], hh[1], hh[2], hh[3]);
            *(uint4*)(sAh + 16) = make_uint4(hh[4], hh[5], hh[6], hh[7]);
            *(uint4*)(sAl)      = make_uint4(ll[0], ll[1], ll[2], ll[3]);
            *(uint4*)(sAl + 16) = make_uint4(ll[4], ll[5], ll[6], ll[7]);
        }
    }

    // ---------------- epilogue ----------------
    {
        const int row = lane >> 2, col2 = (lane & 3) * 2;
        const int nb = n0 + wn * 64;
#pragma unroll
        for (int nt = 0; nt < 8; nt++) {
            const int n = nb + nt * 8 + col2;
            const float b0 = __ldg(bias + n);
            const float b1 = __ldg(bias + n + 1);
#pragma unroll
            for (int mt = 0; mt < 2; mt++) {
                const int m = m0 + wm * 32 + mt * 16 + row;
                if (m < MROWS)
                    *(float2*)(C + (size_t)m * HDIM + n) =
                        make_float2(d[mt][nt][0] + b0, d[mt][nt][1] + b1);
                if (m + 8 < MROWS)
                    *(float2*)(C + (size_t)(m + 8) * HDIM + n) =
                        make_float2(d[mt][nt][2] + b0, d[mt][nt][3] + b1);
            }
        }
    }
}

// ===================== mask + L2 normalize colbert rows =====================
__global__ __launch_bounds__(256)
void colbert_norm(float* __restrict__ C, const float* __restrict__ mask) {
    const int r = blockIdx.x;
    const int b = r / SM1;
    const int s = r - b * SM1 + 1;
    const float mk = mask[b * SEQ + s];
    float4* row = (float4*)(C + (size_t)r * HDIM);
    const int t = threadIdx.x;
    float4 v = row[t];
    v.x *= mk; v.y *= mk; v.z *= mk; v.w *= mk;
    float ss = v.x * v.x + v.y * v.y + v.z * v.z + v.w * v.w;
#pragma unroll
    for (int o = 16; o > 0; o >>= 1) ss += __shfl_xor_sync(0xFFFFFFFFu, ss, o);
    __shared__ float ws[8];
    __shared__ float sscale;
    if ((t & 31) == 0) ws[t >> 5] = ss;
    __syncthreads();
    if (t == 0) {
        float tot = 0.f;
#pragma unroll
        for (int i = 0; i < 8; i++) tot += ws[i];
        sscale = 1.f / fmaxf(sqrtf(tot), EPSN);
    }
    __syncthreads();
    const float sc = sscale;
    v.x *= sc; v.y *= sc; v.z *= sc; v.w *= sc;
    row[t] = v;
}

// ===================== dense head =====================
__global__ __launch_bounds__(256)
void dense_norm(const float* __restrict__ hs, float* __restrict__ o) {
    const int b = blockIdx.x;
    const int t = threadIdx.x;
    const float4* row = (const float4*)(hs + (size_t)b * SEQ * HDIM);
    float4 v = row[t];
    float ss = v.x * v.x + v.y * v.y + v.z * v.z + v.w * v.w;
#pragma unroll
    for (int o2 = 16; o2 > 0; o2 >>= 1) ss += __shfl_xor_sync(0xFFFFFFFFu, ss, o2);
    __shared__ float ws[8];
    __shared__ float sscale;
    if ((t & 31) == 0) ws[t >> 5] = ss;
    __syncthreads();
    if (t == 0) {
        float tot = 0.f;
#pragma unroll
        for (int i = 0; i < 8; i++) tot += ws[i];
        sscale = 1.f / fmaxf(sqrtf(tot), EPSN);
    }
    __syncthreads();
    const float sc = sscale;
    v.x *= sc; v.y *= sc; v.z *= sc; v.w *= sc;
    ((float4*)(o + (size_t)b * HDIM))[t] = v;
}

// ===================== sparse head =====================
__global__ __launch_bounds__(512)
void sparse_zero(float4* __restrict__ p) {
    const int n = (BATCH * VOCAB) / 4;  // exact
    const float4 z = make_float4(0.f, 0.f, 0.f, 0.f);
    for (int i = blockIdx.x * blockDim.x + threadIdx.x; i < n; i += gridDim.x * blockDim.x)
        p[i] = z;
}

__global__ __launch_bounds__(256)
void sparse_scatter(const float* __restrict__ hs, const int* __restrict__ idw,
                    const float* __restrict__ sw, const float* __restrict__ sb,
                    float* __restrict__ sp) {
    __shared__ float wsh[HDIM];
    const int t = threadIdx.x;
    ((float4*)wsh)[t] = ((const float4*)sw)[t];
    __syncthreads();

    const int lane = t & 31;
    const int wp   = t >> 5;

    // int64-vs-int32 layout detection (int64 ids < 2^31 have zero high words)
    const int odd = idw[2 * lane + 1];
    const bool is64 = __all_sync(0xFFFFFFFFu, odd == 0);

    const int tok = blockIdx.x * 8 + wp;
    const float* row = hs + (size_t)tok * HDIM;
    float s = 0.f;
#pragma unroll
    for (int j = 0; j < 8; j++) {
        const float4 h  = *(const float4*)(row + lane * 4 + j * 128);
        const float4 ww = *(const float4*)(wsh + lane * 4 + j * 128);
        s += h.x * ww.x + h.y * ww.y + h.z * ww.z + h.w * ww.w;
    }
#pragma unroll
    for (int o = 16; o > 0; o >>= 1) s += __shfl_xor_sync(0xFFFFFFFFu, s, o);

    if (lane == 0) {
        const float val = s + sb[0];
        if (val > 0.f) {
            long long id = is64 ? ((const long long*)idw)[tok] : (long long)idw[tok];
            if (id >= 0 && id < VOCAB) {
                const int b = tok >> 11;
                atomicMax((int*)&sp[(size_t)b * VOCAB + (int)id], __float_as_int(val));
            }
        }
    }
}

__global__ void zero_special(float* __restrict__ sp) {
    const int t = threadIdx.x;  // 64 threads
    const int ids[4] = {0, 2, 1, 3};
    const int b = t >> 2;
    if (b < BATCH) sp[(size_t)b * VOCAB + ids[t & 3]] = 0.f;
}

// ===================== launch =====================
extern "C" void kernel_launch(void* const* d_in, const int* in_sizes, int n_in,
                              void* d_out, int out_size) {
    const float* hs   = (const float*)d_in[0];
    const float* mask = (const float*)d_in[1];
    const int*   ids  = (const int*)d_in[2];
    const float* sW   = (const float*)d_in[3];
    const float* sbp  = (const float*)d_in[4];
    const float* cW   = (const float*)d_in[5];
    const float* cb   = (const float*)d_in[6];

    float* out      = (float*)d_out;
    float* o_dense  = out;
    float* o_sparse = out + (size_t)BATCH * HDIM;
    float* o_col    = o_sparse + (size_t)BATCH * VOCAB;

    cudaFuncSetAttribute(colbert_gemm_mma, cudaFuncAttributeMaxDynamicSharedMemorySize, GEMM_SMEM);

    dense_norm<<<BATCH, 256>>>(hs, o_dense);
    sparse_zero<<<2048, 512>>>((float4*)o_sparse);
    sparse_scatter<<<(BATCH * SEQ) / 8, 256>>>(hs, ids, sW, sbp, o_sparse);
    zero_special<<<1, 64>>>(o_sparse);

    prep_w<<<dim3(32, 32), dim3(32, 8)>>>(cW);

    dim3 grid(HDIM / BN, (MROWS + BM - 1) / BM);   // (8, 256)
    colbert_gemm_mma<<<grid, 256, GEMM_SMEM>>>(hs, cb, o_col);

    colbert_norm<<<MROWS, 256>>>(o_col, mask);
}

// round 11
// speedup vs baseline: 1.9929x; 1.0158x over previous
#include <cuda_runtime.h>
#include <cuda_bf16.h>
#include <cstdint>

#define VOCAB   250002
#define BATCH   16
#define SEQ     2048
#define HDIM    1024
#define SM1     2047               // SEQ-1
#define MROWS   (BATCH * SM1)      // 32752
#define NTOK    (BATCH * SEQ)      // 32768
#define EPSN    1e-12f

// ===================== small helpers =====================
static __device__ __forceinline__ uint32_t smem_u32(const void* p) {
    uint32_t a;
    asm("{ .reg .u64 t; cvta.to.shared.u64 t, %1; cvt.u32.u64 %0, t; }" : "=r"(a) : "l"(p));
    return a;
}
// pack two floats to bf16x2 (first arg -> low half)
static __device__ __forceinline__ unsigned bpack(float lo, float hi) {
    unsigned r;
    asm("cvt.rn.bf16x2.f32 %0, %1, %2;" : "=r"(r) : "f"(hi), "f"(lo));
    return r;
}

#define CP_ASYNC16(s, g) \
    asm volatile("cp.async.cg.shared.global [%0], [%1], 16;" :: "r"(s), "l"(g))
#define CP_COMMIT()  asm volatile("cp.async.commit_group;" ::: "memory")
#define CP_WAIT2()   asm volatile("cp.async.wait_group 2;" ::: "memory")

#define LDSM4(R, a) \
    asm volatile("ldmatrix.sync.aligned.m8n8.x4.shared.b16 {%0,%1,%2,%3}, [%4];" \
        : "=r"((R)[0]), "=r"((R)[1]), "=r"((R)[2]), "=r"((R)[3]) : "r"(a))

#define MMA16816(D, A, B0, B1) \
    asm volatile("mma.sync.aligned.m16n8k16.row.col.f32.bf16.bf16.f32 " \
        "{%0,%1,%2,%3}, {%4,%5,%6,%7}, {%8,%9}, {%0,%1,%2,%3};" \
        : "+f"((D)[0]), "+f"((D)[1]), "+f"((D)[2]), "+f"((D)[3]) \
        : "r"((A)[0]), "r"((A)[1]), "r"((A)[2]), "r"((A)[3]), "r"(B0), "r"(B1))

// ===================== device scratch =====================
__device__ __nv_bfloat16 g_Wt_hi[HDIM * HDIM];   // [N, K] K-contig
__device__ __nv_bfloat16 g_Wt_lo[HDIM * HDIM];
__device__ __nv_bfloat16 g_Ah[(size_t)NTOK * HDIM];  // hidden hi plane, token order
__device__ __nv_bfloat16 g_Al[(size_t)NTOK * HDIM];  // hidden lo plane

// ===================== W pre-transpose + hi/lo split =====================
__global__ __launch_bounds__(256)
void prep_w(const float* __restrict__ W) {
    __shared__ float tile[32][33];
    const int tx = threadIdx.x, ty = threadIdx.y;     // (32, 8)
    const int n0 = blockIdx.x * 32, k0 = blockIdx.y * 32;
#pragma unroll
    for (int i = 0; i < 32; i += 8)
        tile[ty + i][tx] = W[(size_t)(k0 + ty + i) * HDIM + n0 + tx];
    __syncthreads();
#pragma unroll
    for (int i = 0; i < 32; i += 8) {
        const int n = n0 + ty + i, k = k0 + tx;
        float v = tile[tx][ty + i];
        __nv_bfloat16 h = __float2bfloat16_rn(v);
        float r = v - __bfloat162float(h);
        g_Wt_hi[(size_t)n * HDIM + k] = h;
        g_Wt_lo[(size_t)n * HDIM + k] = __float2bfloat16_rn(r);
    }
}

// ===================== fused: A hi/lo split + sparse head =====================
// one warp per token: convert row to bf16 hi/lo planes AND compute sparse dot,
// relu, scatter-max into the vocab grid.
__global__ __launch_bounds__(256)
void split_scatter(const float* __restrict__ hs, const int* __restrict__ idw,
                   const float* __restrict__ sw, const float* __restrict__ sb,
                   float* __restrict__ sp) {
    __shared__ float wsh[HDIM];
    const int t = threadIdx.x;
    ((float4*)wsh)[t] = ((const float4*)sw)[t];
    __syncthreads();

    const int lane = t & 31;
    const int wp   = t >> 5;

    // int64-vs-int32 layout detection (int64 ids < 2^31 have zero high words)
    const int odd = idw[2 * lane + 1];
    const bool is64 = __all_sync(0xFFFFFFFFu, odd == 0);

    const int tok = blockIdx.x * 8 + wp;
    const float* row = hs + (size_t)tok * HDIM;
    __nv_bfloat16* ah = g_Ah + (size_t)tok * HDIM;
    __nv_bfloat16* al = g_Al + (size_t)tok * HDIM;

    float s = 0.f;
#pragma unroll
    for (int j = 0; j < 8; j++) {
        const int off = lane * 4 + j * 128;
        const float4 h  = *(const float4*)(row + off);
        const float4 ww = *(const float4*)(wsh + off);
        s += h.x * ww.x + h.y * ww.y + h.z * ww.z + h.w * ww.w;

        unsigned h0 = bpack(h.x, h.y);
        unsigned h1 = bpack(h.z, h.w);
        float rx = h.x - __uint_as_float(h0 << 16);
        float ry = h.y - __uint_as_float(h0 & 0xFFFF0000u);
        float rz = h.z - __uint_as_float(h1 << 16);
        float rw = h.w - __uint_as_float(h1 & 0xFFFF0000u);
        *(uint2*)(ah + off) = make_uint2(h0, h1);
        *(uint2*)(al + off) = make_uint2(bpack(rx, ry), bpack(rz, rw));
    }
#pragma unroll
    for (int o = 16; o > 0; o >>= 1) s += __shfl_xor_sync(0xFFFFFFFFu, s, o);

    if (lane == 0) {
        const float val = s + sb[0];
        if (val > 0.f) {
            long long id = is64 ? ((const long long*)idw)[tok] : (long long)idw[tok];
            if (id >= 0 && id < VOCAB) {
                const int b = tok >> 11;
                atomicMax((int*)&sp[(size_t)b * VOCAB + (int)id], __float_as_int(val));
            }
        }
    }
}

// ===================== colbert GEMM via mma.sync bf16 (3-term split) =====================
// C[m,n] = A[mrow(m),:] . W[:,n] + bias[n],  mrow(m) = m + m/2047 + 1
#define BM 128
#define BN 128
#define BKC 32                       // bf16 k per chunk
#define NC  (HDIM / BKC)             // 32 chunks
#define STAGES 4
#define ROWB 80                      // padded smem row bytes (32 bf16 data + 16B pad)
#define PLANE (BM * ROWB)            // 10240 B
#define STAGE (4 * PLANE)            // Ah, Al, Bh, Bl = 40960 B
#define GEMM_SMEM (STAGES * STAGE)   // 163840 B

__global__ __launch_bounds__(256, 1)
void colbert_gemm_mma(const float* __restrict__ bias, float* __restrict__ C) {
    extern __shared__ char smem[];
    const uint32_t sb = smem_u32(smem);
    const int t = threadIdx.x, lane = t & 31, wid = t >> 5;
    const int m0 = blockIdx.y * BM;
    const int n0 = blockIdx.x * BN;

    // ---- load mapping (per thread): row lr = t>>1, 32B half lh = t&1 ----
    const int lr = t >> 1, lh = t & 1;
    const int am = m0 + lr;
    const int arow = (am < MROWS) ? (am + am / SM1 + 1) : 0;
    const __nv_bfloat16* gah = g_Ah + (size_t)arow * HDIM + lh * 16;
    const __nv_bfloat16* gal = g_Al + (size_t)arow * HDIM + lh * 16;
    const __nv_bfloat16* gbh = g_Wt_hi + (size_t)(n0 + lr) * HDIM + lh * 16;
    const __nv_bfloat16* gbl = g_Wt_lo + (size_t)(n0 + lr) * HDIM + lh * 16;
    const uint32_t s_row = (uint32_t)lr * ROWB + (uint32_t)lh * 32;

    // ---- warp compute mapping: 4(m) x 2(n) warps; warp tile 32x64 ----
    const int wm = wid >> 1, wn = wid & 1;
    const uint32_t a_r  = (uint32_t)((lane & 7) + ((lane >> 3) & 1) * 8);
    const uint32_t a_kb = (uint32_t)((lane >> 4) * 16);
    const uint32_t b_r  = (uint32_t)((lane & 7) + ((lane >> 4) & 1) * 8);
    const uint32_t b_kb = (uint32_t)(((lane >> 3) & 1) * 16);

    float d[2][8][4];
#pragma unroll
    for (int i = 0; i < 2; i++)
#pragma unroll
        for (int j = 0; j < 8; j++)
#pragma unroll
            for (int q = 0; q < 4; q++) d[i][j][q] = 0.f;

    // ---- per-chunk load issue ----
#define ISSUE_LOADS(c) do {                                                  \
        const int _c = (c);                                                  \
        const uint32_t _sA = sb + (uint32_t)(_c & (STAGES - 1)) * STAGE + s_row; \
        const uint32_t _sB = _sA + 2 * PLANE;                                \
        const __nv_bfloat16* _ah = gah + _c * BKC;                           \
        const __nv_bfloat16* _al = gal + _c * BKC;                           \
        const __nv_bfloat16* _bh = gbh + _c * BKC;                           \
        const __nv_bfloat16* _bl = gbl + _c * BKC;                           \
        CP_ASYNC16(_sA,              _ah);                                   \
        CP_ASYNC16(_sA + 16,         _ah + 8);                               \
        CP_ASYNC16(_sA + PLANE,      _al);                                   \
        CP_ASYNC16(_sA + PLANE + 16, _al + 8);                               \
        CP_ASYNC16(_sB,              _bh);                                   \
        CP_ASYNC16(_sB + 16,         _bh + 8);                               \
        CP_ASYNC16(_sB + PLANE,      _bl);                                   \
        CP_ASYNC16(_sB + PLANE + 16, _bl + 8);                               \
    } while (0)

    // ---- prologue: fill STAGES-1 stages ----
#pragma unroll
    for (int c = 0; c < STAGES - 1; c++) {
        ISSUE_LOADS(c);
        CP_COMMIT();
    }

    // ---- main loop ----
    for (int c = 0; c < NC; c++) {
        CP_WAIT2();
        __syncthreads();

        if (c + STAGES - 1 < NC) ISSUE_LOADS(c + STAGES - 1);
        CP_COMMIT();

        const uint32_t st = sb + (uint32_t)(c & (STAGES - 1)) * STAGE;
        const uint32_t aA = st + (uint32_t)(wm * 32) * ROWB + a_r * ROWB + a_kb;
        const uint32_t aB = st + 2 * PLANE + (uint32_t)(wn * 64) * ROWB + b_r * ROWB + b_kb;
#pragma unroll
        for (int k16 = 0; k16 < 2; k16++) {
            const uint32_t ko = (uint32_t)(k16 * 32);
            unsigned ah[2][4], al[2][4], bh[4][4], bl[4][4];
#pragma unroll
            for (int mt = 0; mt < 2; mt++) {
                LDSM4(ah[mt], aA + (uint32_t)(mt * 16) * ROWB + ko);
                LDSM4(al[mt], aA + (uint32_t)(mt * 16) * ROWB + ko + PLANE);
            }
#pragma unroll
            for (int p = 0; p < 4; p++) {
                LDSM4(bh[p], aB + (uint32_t)(p * 16) * ROWB + ko);
                LDSM4(bl[p], aB + (uint32_t)(p * 16) * ROWB + ko + PLANE);
            }
#pragma unroll
            for (int mt = 0; mt < 2; mt++)
#pragma unroll
                for (int p = 0; p < 4; p++) {
                    MMA16816(d[mt][2 * p],     ah[mt], bh[p][0], bh[p][1]);
                    MMA16816(d[mt][2 * p + 1], ah[mt], bh[p][2], bh[p][3]);
                    MMA16816(d[mt][2 * p],     ah[mt], bl[p][0], bl[p][1]);
                    MMA16816(d[mt][2 * p + 1], ah[mt], bl[p][2], bl[p][3]);
                    MMA16816(d[mt][2 * p],     al[mt], bh[p][0], bh[p][1]);
                    MMA16816(d[mt][2 * p + 1], al[mt], bh[p][2], bh[p][3]);
                }
        }
    }
#undef ISSUE_LOADS

    // ---------------- epilogue ----------------
    {
        const int row = lane >> 2, col2 = (lane & 3) * 2;
        const int nb = n0 + wn * 64;
#pragma unroll
        for (int nt = 0; nt < 8; nt++) {
            const int n = nb + nt * 8 + col2;
            const float b0 = __ldg(bias + n);
            const float b1 = __ldg(bias + n + 1);
#pragma unroll
            for (int mt = 0; mt < 2; mt++) {
                const int m = m0 + wm * 32 + mt * 16 + row;
                if (m < MROWS)
                    *(float2*)(C + (size_t)m * HDIM + n) =
                        make_float2(d[mt][nt][0] + b0, d[mt][nt][1] + b1);
                if (m + 8 < MROWS)
                    *(float2*)(C + (size_t)(m + 8) * HDIM + n) =
                        make_float2(d[mt][nt][2] + b0, d[mt][nt][3] + b1);
            }
        }
    }
}

// ===================== mask + L2 normalize colbert rows =====================
__global__ __launch_bounds__(256)
void colbert_norm(float* __restrict__ C, const float* __restrict__ mask) {
    const int r = blockIdx.x;
    const int b = r / SM1;
    const int s = r - b * SM1 + 1;
    const float mk = mask[b * SEQ + s];
    float4* row = (float4*)(C + (size_t)r * HDIM);
    const int t = threadIdx.x;
    float4 v = row[t];
    v.x *= mk; v.y *= mk; v.z *= mk; v.w *= mk;
    float ss = v.x * v.x + v.y * v.y + v.z * v.z + v.w * v.w;
#pragma unroll
    for (int o = 16; o > 0; o >>= 1) ss += __shfl_xor_sync(0xFFFFFFFFu, ss, o);
    __shared__ float ws[8];
    __shared__ float sscale;
    if ((t & 31) == 0) ws[t >> 5] = ss;
    __syncthreads();
    if (t == 0) {
        float tot = 0.f;
#pragma unroll
        for (int i = 0; i < 8; i++) tot += ws[i];
        sscale = 1.f / fmaxf(sqrtf(tot), EPSN);
    }
    __syncthreads();
    const float sc = sscale;
    v.x *= sc; v.y *= sc; v.z *= sc; v.w *= sc;
    row[t] = v;
}

// ===================== dense head =====================
__global__ __launch_bounds__(256)
void dense_norm(const float* __restrict__ hs, float* __restrict__ o) {
    const int b = blockIdx.x;
    const int t = threadIdx.x;
    const float4* row = (const float4*)(hs + (size_t)b * SEQ * HDIM);
    float4 v = row[t];
    float ss = v.x * v.x + v.y * v.y + v.z * v.z + v.w * v.w;
#pragma unroll
    for (int o2 = 16; o2 > 0; o2 >>= 1) ss += __shfl_xor_sync(0xFFFFFFFFu, ss, o2);
    __shared__ float ws[8];
    __shared__ float sscale;
    if ((t & 31) == 0) ws[t >> 5] = ss;
    __syncthreads();
    if (t == 0) {
        float tot = 0.f;
#pragma unroll
        for (int i = 0; i < 8; i++) tot += ws[i];
        sscale = 1.f / fmaxf(sqrtf(tot), EPSN);
    }
    __syncthreads();
    const float sc = sscale;
    v.x *= sc; v.y *= sc; v.z *= sc; v.w *= sc;
    ((float4*)(o + (size_t)b * HDIM))[t] = v;
}

// ===================== sparse zero / special =====================
__global__ __launch_bounds__(512)
void sparse_zero(float4* __restrict__ p) {
    const int n = (BATCH * VOCAB) / 4;  // exact
    const float4 z = make_float4(0.f, 0.f, 0.f, 0.f);
    for (int i = blockIdx.x * blockDim.x + threadIdx.x; i < n; i += gridDim.x * blockDim.x)
        p[i] = z;
}

__global__ void zero_special(float* __restrict__ sp) {
    const int t = threadIdx.x;  // 64 threads
    const int ids[4] = {0, 2, 1, 3};
    const int b = t >> 2;
    if (b < BATCH) sp[(size_t)b * VOCAB + ids[t & 3]] = 0.f;
}

// ===================== launch =====================
extern "C" void kernel_launch(void* const* d_in, const int* in_sizes, int n_in,
                              void* d_out, int out_size) {
    const float* hs   = (const float*)d_in[0];
    const float* mask = (const float*)d_in[1];
    const int*   ids  = (const int*)d_in[2];
    const float* sW   = (const float*)d_in[3];
    const float* sbp  = (const float*)d_in[4];
    const float* cW   = (const float*)d_in[5];
    const float* cb   = (const float*)d_in[6];

    float* out      = (float*)d_out;
    float* o_dense  = out;
    float* o_sparse = out + (size_t)BATCH * HDIM;
    float* o_col    = o_sparse + (size_t)BATCH * VOCAB;

    cudaFuncSetAttribute(colbert_gemm_mma, cudaFuncAttributeMaxDynamicSharedMemorySize, GEMM_SMEM);

    dense_norm<<<BATCH, 256>>>(hs, o_dense);
    sparse_zero<<<2048, 512>>>((float4*)o_sparse);
    prep_w<<<dim3(32, 32), dim3(32, 8)>>>(cW);
    split_scatter<<<NTOK / 8, 256>>>(hs, ids, sW, sbp, o_sparse);
    zero_special<<<1, 64>>>(o_sparse);

    dim3 grid(HDIM / BN, (MROWS + BM - 1) / BM);   // (8, 256)
    colbert_gemm_mma<<<grid, 256, GEMM_SMEM>>>(cb, o_col);

    colbert_norm<<<MROWS, 256>>>(o_col, mask);
}

// round 12
// speedup vs baseline: 1.9943x; 1.0007x over previous
#include <cuda_runtime.h>
#include <cuda_bf16.h>
#include <cstdint>

#define VOCAB   250002
#define BATCH   16
#define SEQ     2048
#define HDIM    1024
#define SM1     2047               // SEQ-1
#define MROWS   (BATCH * SM1)      // 32752
#define NTOK    (BATCH * SEQ)      // 32768
#define EPSN    1e-12f

// ===================== small helpers =====================
static __device__ __forceinline__ uint32_t smem_u32(const void* p) {
    uint32_t a;
    asm("{ .reg .u64 t; cvta.to.shared.u64 t, %1; cvt.u32.u64 %0, t; }" : "=r"(a) : "l"(p));
    return a;
}
// pack two floats to bf16x2 (first arg -> low half)
static __device__ __forceinline__ unsigned bpack(float lo, float hi) {
    unsigned r;
    asm("cvt.rn.bf16x2.f32 %0, %1, %2;" : "=r"(r) : "f"(hi), "f"(lo));
    return r;
}

#define CP_ASYNC16(s, g) \
    asm volatile("cp.async.cg.shared.global [%0], [%1], 16;" :: "r"(s), "l"(g))
#define CP_COMMIT()  asm volatile("cp.async.commit_group;" ::: "memory")
#define CP_WAIT2()   asm volatile("cp.async.wait_group 2;" ::: "memory")

#define LDSM4(R, a) \
    asm volatile("ldmatrix.sync.aligned.m8n8.x4.shared.b16 {%0,%1,%2,%3}, [%4];" \
        : "=r"((R)[0]), "=r"((R)[1]), "=r"((R)[2]), "=r"((R)[3]) : "r"(a))

#define MMA16816(D, A, B0, B1) \
    asm volatile("mma.sync.aligned.m16n8k16.row.col.f32.bf16.bf16.f32 " \
        "{%0,%1,%2,%3}, {%4,%5,%6,%7}, {%8,%9}, {%0,%1,%2,%3};" \
        : "+f"((D)[0]), "+f"((D)[1]), "+f"((D)[2]), "+f"((D)[3]) \
        : "r"((A)[0]), "r"((A)[1]), "r"((A)[2]), "r"((A)[3]), "r"(B0), "r"(B1))

// ===================== device scratch =====================
__device__ __nv_bfloat16 g_Wt_hi[HDIM * HDIM];   // [N, K] K-contig
__device__ __nv_bfloat16 g_Wt_lo[HDIM * HDIM];
__device__ __nv_bfloat16 g_Ah[(size_t)NTOK * HDIM];  // hidden hi plane, token order
__device__ __nv_bfloat16 g_Al[(size_t)NTOK * HDIM];  // hidden lo plane

// ===================== W pre-transpose + hi/lo split =====================
__global__ __launch_bounds__(256)
void prep_w(const float* __restrict__ W) {
    __shared__ float tile[32][33];
    const int tx = threadIdx.x, ty = threadIdx.y;     // (32, 8)
    const int n0 = blockIdx.x * 32, k0 = blockIdx.y * 32;
#pragma unroll
    for (int i = 0; i < 32; i += 8)
        tile[ty + i][tx] = W[(size_t)(k0 + ty + i) * HDIM + n0 + tx];
    __syncthreads();
#pragma unroll
    for (int i = 0; i < 32; i += 8) {
        const int n = n0 + ty + i, k = k0 + tx;
        float v = tile[tx][ty + i];
        __nv_bfloat16 h = __float2bfloat16_rn(v);
        float r = v - __bfloat162float(h);
        g_Wt_hi[(size_t)n * HDIM + k] = h;
        g_Wt_lo[(size_t)n * HDIM + k] = __float2bfloat16_rn(r);
    }
}

// ===================== fused: A hi/lo split + sparse head =====================
__global__ __launch_bounds__(256)
void split_scatter(const float* __restrict__ hs, const int* __restrict__ idw,
                   const float* __restrict__ sw, const float* __restrict__ sb,
                   float* __restrict__ sp) {
    __shared__ float wsh[HDIM];
    const int t = threadIdx.x;
    ((float4*)wsh)[t] = ((const float4*)sw)[t];
    __syncthreads();

    const int lane = t & 31;
    const int wp   = t >> 5;

    // int64-vs-int32 layout detection (int64 ids < 2^31 have zero high words)
    const int odd = idw[2 * lane + 1];
    const bool is64 = __all_sync(0xFFFFFFFFu, odd == 0);

    const int tok = blockIdx.x * 8 + wp;
    const float* row = hs + (size_t)tok * HDIM;
    __nv_bfloat16* ah = g_Ah + (size_t)tok * HDIM;
    __nv_bfloat16* al = g_Al + (size_t)tok * HDIM;

    float s = 0.f;
#pragma unroll
    for (int j = 0; j < 8; j++) {
        const int off = lane * 4 + j * 128;
        const float4 h  = *(const float4*)(row + off);
        const float4 ww = *(const float4*)(wsh + off);
        s += h.x * ww.x + h.y * ww.y + h.z * ww.z + h.w * ww.w;

        unsigned h0 = bpack(h.x, h.y);
        unsigned h1 = bpack(h.z, h.w);
        float rx = h.x - __uint_as_float(h0 << 16);
        float ry = h.y - __uint_as_float(h0 & 0xFFFF0000u);
        float rz = h.z - __uint_as_float(h1 << 16);
        float rw = h.w - __uint_as_float(h1 & 0xFFFF0000u);
        *(uint2*)(ah + off) = make_uint2(h0, h1);
        *(uint2*)(al + off) = make_uint2(bpack(rx, ry), bpack(rz, rw));
    }
#pragma unroll
    for (int o = 16; o > 0; o >>= 1) s += __shfl_xor_sync(0xFFFFFFFFu, s, o);

    if (lane == 0) {
        const float val = s + sb[0];
        if (val > 0.f) {
            long long id = is64 ? ((const long long*)idw)[tok] : (long long)idw[tok];
            if (id >= 0 && id < VOCAB) {
                const int b = tok >> 11;
                atomicMax((int*)&sp[(size_t)b * VOCAB + (int)id], __float_as_int(val));
            }
        }
    }
}

// ===================== colbert GEMM via mma.sync bf16 (3-term split) =====================
// C[m,n] = A[mrow(m),:] . W[:,n] + bias[n],  mrow(m) = m + m/2047 + 1
#define BM 128
#define BN 128
#define BKC 32                       // bf16 k per chunk
#define NC  (HDIM / BKC)             // 32 chunks
#define STAGES 4
#define ROWB 80                      // padded smem row bytes (32 bf16 data + 16B pad)
#define PLANE (BM * ROWB)            // 10240 B
#define STAGE (4 * PLANE)            // Ah, Al, Bh, Bl = 40960 B
#define GEMM_SMEM (STAGES * STAGE)   // 163840 B

__global__ __launch_bounds__(256, 1)
void colbert_gemm_mma(const float* __restrict__ bias, float* __restrict__ C) {
    extern __shared__ char smem[];
    const uint32_t sb = smem_u32(smem);
    const int t = threadIdx.x, lane = t & 31, wid = t >> 5;
    const int m0 = blockIdx.y * BM;
    const int n0 = blockIdx.x * BN;

    // ---- load mapping (per thread): row lr = t>>1, 32B half lh = t&1 ----
    const int lr = t >> 1, lh = t & 1;
    const int am = m0 + lr;
    const int arow = (am < MROWS) ? (am + am / SM1 + 1) : 0;
    const __nv_bfloat16* gah = g_Ah + (size_t)arow * HDIM + lh * 16;
    const __nv_bfloat16* gal = g_Al + (size_t)arow * HDIM + lh * 16;
    const __nv_bfloat16* gbh = g_Wt_hi + (size_t)(n0 + lr) * HDIM + lh * 16;
    const __nv_bfloat16* gbl = g_Wt_lo + (size_t)(n0 + lr) * HDIM + lh * 16;
    const uint32_t s_row = (uint32_t)lr * ROWB + (uint32_t)lh * 32;

    // ---- warp compute mapping: 4(m) x 2(n) warps; warp tile 32x64 ----
    const int wm = wid >> 1, wn = wid & 1;
    const uint32_t a_r  = (uint32_t)((lane & 7) + ((lane >> 3) & 1) * 8);
    const uint32_t a_kb = (uint32_t)((lane >> 4) * 16);
    const uint32_t b_r  = (uint32_t)((lane & 7) + ((lane >> 4) & 1) * 8);
    const uint32_t b_kb = (uint32_t)(((lane >> 3) & 1) * 16);

    float d[2][8][4];
#pragma unroll
    for (int i = 0; i < 2; i++)
#pragma unroll
        for (int j = 0; j < 8; j++)
#pragma unroll
            for (int q = 0; q < 4; q++) d[i][j][q] = 0.f;

    // ---- per-chunk load issue ----
#define ISSUE_LOADS(c) do {                                                  \
        const int _c = (c);                                                  \
        const uint32_t _sA = sb + (uint32_t)(_c & (STAGES - 1)) * STAGE + s_row; \
        const uint32_t _sB = _sA + 2 * PLANE;                                \
        const __nv_bfloat16* _ah = gah + _c * BKC;                           \
        const __nv_bfloat16* _al = gal + _c * BKC;                           \
        const __nv_bfloat16* _bh = gbh + _c * BKC;                           \
        const __nv_bfloat16* _bl = gbl + _c * BKC;                           \
        CP_ASYNC16(_sA,              _ah);                                   \
        CP_ASYNC16(_sA + 16,         _ah + 8);                               \
        CP_ASYNC16(_sA + PLANE,      _al);                                   \
        CP_ASYNC16(_sA + PLANE + 16, _al + 8);                               \
        CP_ASYNC16(_sB,              _bh);                                   \
        CP_ASYNC16(_sB + 16,         _bh + 8);                               \
        CP_ASYNC16(_sB + PLANE,      _bl);                                   \
        CP_ASYNC16(_sB + PLANE + 16, _bl + 8);                               \
    } while (0)

    // ---- prologue: fill STAGES-1 stages ----
#pragma unroll
    for (int c = 0; c < STAGES - 1; c++) {
        ISSUE_LOADS(c);
        CP_COMMIT();
    }

    // ---- main loop ----
    for (int c = 0; c < NC; c++) {
        CP_WAIT2();
        __syncthreads();

        if (c + STAGES - 1 < NC) ISSUE_LOADS(c + STAGES - 1);
        CP_COMMIT();

        const uint32_t st = sb + (uint32_t)(c & (STAGES - 1)) * STAGE;
        const uint32_t aA = st + (uint32_t)(wm * 32) * ROWB + a_r * ROWB + a_kb;
        const uint32_t aB = st + 2 * PLANE + (uint32_t)(wn * 64) * ROWB + b_r * ROWB + b_kb;
#pragma unroll
        for (int k16 = 0; k16 < 2; k16++) {
            const uint32_t ko = (uint32_t)(k16 * 32);
            unsigned ah[2][4], al[2][4], bh[4][4], bl[4][4];
#pragma unroll
            for (int mt = 0; mt < 2; mt++) {
                LDSM4(ah[mt], aA + (uint32_t)(mt * 16) * ROWB + ko);
                LDSM4(al[mt], aA + (uint32_t)(mt * 16) * ROWB + ko + PLANE);
            }
#pragma unroll
            for (int p = 0; p < 4; p++) {
                LDSM4(bh[p], aB + (uint32_t)(p * 16) * ROWB + ko);
                LDSM4(bl[p], aB + (uint32_t)(p * 16) * ROWB + ko + PLANE);
            }
            // ---- term-major schedule: accumulator reuse distance = 16 MMAs ----
            // term 1: a_hi * b_hi
#pragma unroll
            for (int mt = 0; mt < 2; mt++)
#pragma unroll
                for (int p = 0; p < 4; p++) {
                    MMA16816(d[mt][2 * p],     ah[mt], bh[p][0], bh[p][1]);
                    MMA16816(d[mt][2 * p + 1], ah[mt], bh[p][2], bh[p][3]);
                }
            // term 2: a_hi * b_lo
#pragma unroll
            for (int mt = 0; mt < 2; mt++)
#pragma unroll
                for (int p = 0; p < 4; p++) {
                    MMA16816(d[mt][2 * p],     ah[mt], bl[p][0], bl[p][1]);
                    MMA16816(d[mt][2 * p + 1], ah[mt], bl[p][2], bl[p][3]);
                }
            // term 3: a_lo * b_hi
#pragma unroll
            for (int mt = 0; mt < 2; mt++)
#pragma unroll
                for (int p = 0; p < 4; p++) {
                    MMA16816(d[mt][2 * p],     al[mt], bh[p][0], bh[p][1]);
                    MMA16816(d[mt][2 * p + 1], al[mt], bh[p][2], bh[p][3]);
                }
        }
    }
#undef ISSUE_LOADS

    // ---------------- epilogue ----------------
    {
        const int row = lane >> 2, col2 = (lane & 3) * 2;
        const int nb = n0 + wn * 64;
#pragma unroll
        for (int nt = 0; nt < 8; nt++) {
            const int n = nb + nt * 8 + col2;
            const float b0 = __ldg(bias + n);
            const float b1 = __ldg(bias + n + 1);
#pragma unroll
            for (int mt = 0; mt < 2; mt++) {
                const int m = m0 + wm * 32 + mt * 16 + row;
                if (m < MROWS)
                    *(float2*)(C + (size_t)m * HDIM + n) =
                        make_float2(d[mt][nt][0] + b0, d[mt][nt][1] + b1);
                if (m + 8 < MROWS)
                    *(float2*)(C + (size_t)(m + 8) * HDIM + n) =
                        make_float2(d[mt][nt][2] + b0, d[mt][nt][3] + b1);
            }
        }
    }
}

// ===================== mask + L2 normalize colbert rows =====================
__global__ __launch_bounds__(256)
void colbert_norm(float* __restrict__ C, const float* __restrict__ mask) {
    const int r = blockIdx.x;
    const int b = r / SM1;
    const int s = r - b * SM1 + 1;
    const float mk = mask[b * SEQ + s];
    float4* row = (float4*)(C + (size_t)r * HDIM);
    const int t = threadIdx.x;
    float4 v = row[t];
    v.x *= mk; v.y *= mk; v.z *= mk; v.w *= mk;
    float ss = v.x * v.x + v.y * v.y + v.z * v.z + v.w * v.w;
#pragma unroll
    for (int o = 16; o > 0; o >>= 1) ss += __shfl_xor_sync(0xFFFFFFFFu, ss, o);
    __shared__ float ws[8];
    __shared__ float sscale;
    if ((t & 31) == 0) ws[t >> 5] = ss;
    __syncthreads();
    if (t == 0) {
        float tot = 0.f;
#pragma unroll
        for (int i = 0; i < 8; i++) tot += ws[i];
        sscale = 1.f / fmaxf(sqrtf(tot), EPSN);
    }
    __syncthreads();
    const float sc = sscale;
    v.x *= sc; v.y *= sc; v.z *= sc; v.w *= sc;
    row[t] = v;
}

// ===================== dense head =====================
__global__ __launch_bounds__(256)
void dense_norm(const float* __restrict__ hs, float* __restrict__ o) {
    const int b = blockIdx.x;
    const int t = threadIdx.x;
    const float4* row = (const float4*)(hs + (size_t)b * SEQ * HDIM);
    float4 v = row[t];
    float ss = v.x * v.x + v.y * v.y + v.z * v.z + v.w * v.w;
#pragma unroll
    for (int o2 = 16; o2 > 0; o2 >>= 1) ss += __shfl_xor_sync(0xFFFFFFFFu, ss, o2);
    __shared__ float ws[8];
    __shared__ float sscale;
    if ((t & 31) == 0) ws[t >> 5] = ss;
    __syncthreads();
    if (t == 0) {
        float tot = 0.f;
#pragma unroll
        for (int i = 0; i < 8; i++) tot += ws[i];
        sscale = 1.f / fmaxf(sqrtf(tot), EPSN);
    }
    __syncthreads();
    const float sc = sscale;
    v.x *= sc; v.y *= sc; v.z *= sc; v.w *= sc;
    ((float4*)(o + (size_t)b * HDIM))[t] = v;
}

// ===================== sparse zero / special =====================
__global__ __launch_bounds__(512)
void sparse_zero(float4* __restrict__ p) {
    const int n = (BATCH * VOCAB) / 4;  // exact
    const float4 z = make_float4(0.f, 0.f, 0.f, 0.f);
    for (int i = blockIdx.x * blockDim.x + threadIdx.x; i < n; i += gridDim.x * blockDim.x)
        p[i] = z;
}

__global__ void zero_special(float* __restrict__ sp) {
    const int t = threadIdx.x;  // 64 threads
    const int ids[4] = {0, 2, 1, 3};
    const int b = t >> 2;
    if (b < BATCH) sp[(size_t)b * VOCAB + ids[t & 3]] = 0.f;
}

// ===================== launch =====================
extern "C" void kernel_launch(void* const* d_in, const int* in_sizes, int n_in,
                              void* d_out, int out_size) {
    const float* hs   = (const float*)d_in[0];
    const float* mask = (const float*)d_in[1];
    const int*   ids  = (const int*)d_in[2];
    const float* sW   = (const float*)d_in[3];
    const float* sbp  = (const float*)d_in[4];
    const float* cW   = (const float*)d_in[5];
    const float* cb   = (const float*)d_in[6];

    float* out      = (float*)d_out;
    float* o_dense  = out;
    float* o_sparse = out + (size_t)BATCH * HDIM;
    float* o_col    = o_sparse + (size_t)BATCH * VOCAB;

    cudaFuncSetAttribute(colbert_gemm_mma, cudaFuncAttributeMaxDynamicSharedMemorySize, GEMM_SMEM);

    dense_norm<<<BATCH, 256>>>(hs, o_dense);
    sparse_zero<<<2048, 512>>>((float4*)o_sparse);
    prep_w<<<dim3(32, 32), dim3(32, 8)>>>(cW);
    split_scatter<<<NTOK / 8, 256>>>(hs, ids, sW, sbp, o_sparse);
    zero_special<<<1, 64>>>(o_sparse);

    dim3 grid(HDIM / BN, (MROWS + BM - 1) / BM);   // (8, 256)
    colbert_gemm_mma<<<grid, 256, GEMM_SMEM>>>(cb, o_col);

    colbert_norm<<<MROWS, 256>>>(o_col, mask);
}

// round 13
// speedup vs baseline: 2.7085x; 1.3581x over previous
#include <cuda_runtime.h>
#include <cuda_fp16.h>
#include <cstdint>

#define VOCAB   250002
#define BATCH   16
#define SEQ     2048
#define HDIM    1024
#define SM1     2047               // SEQ-1
#define MROWS   (BATCH * SM1)      // 32752
#define NTOK    (BATCH * SEQ)      // 32768
#define EPSN    1e-12f

// ===================== small helpers =====================
static __device__ __forceinline__ uint32_t smem_u32(const void* p) {
    uint32_t a;
    asm("{ .reg .u64 t; cvta.to.shared.u64 t, %1; cvt.u32.u64 %0, t; }" : "=r"(a) : "l"(p));
    return a;
}
// pack two floats to f16x2 (first arg -> low half)
static __device__ __forceinline__ unsigned hpack(float lo, float hi) {
    unsigned r;
    asm("cvt.rn.f16x2.f32 %0, %1, %2;" : "=r"(r) : "f"(hi), "f"(lo));
    return r;
}

#define CP_ASYNC16(s, g) \
    asm volatile("cp.async.cg.shared.global [%0], [%1], 16;" :: "r"(s), "l"(g))
#define CP_COMMIT()  asm volatile("cp.async.commit_group;" ::: "memory")
#define CP_WAIT2()   asm volatile("cp.async.wait_group 2;" ::: "memory")

#define LDSM4(R, a) \
    asm volatile("ldmatrix.sync.aligned.m8n8.x4.shared.b16 {%0,%1,%2,%3}, [%4];" \
        : "=r"((R)[0]), "=r"((R)[1]), "=r"((R)[2]), "=r"((R)[3]) : "r"(a))

#define MMA16816(D, A, B0, B1) \
    asm volatile("mma.sync.aligned.m16n8k16.row.col.f32.f16.f16.f32 " \
        "{%0,%1,%2,%3}, {%4,%5,%6,%7}, {%8,%9}, {%0,%1,%2,%3};" \
        : "+f"((D)[0]), "+f"((D)[1]), "+f"((D)[2]), "+f"((D)[3]) \
        : "r"((A)[0]), "r"((A)[1]), "r"((A)[2]), "r"((A)[3]), "r"(B0), "r"(B1))

// ===================== device scratch =====================
__device__ __half g_Wt_hi[HDIM * HDIM];            // [N, K] K-contig, fp16 hi
__device__ __half g_Wt_lo[HDIM * HDIM];            // fp16 residual
__device__ __half g_Ah[(size_t)NTOK * HDIM];       // hidden fp16, token order

// ===================== W pre-transpose + fp16 hi/lo split =====================
__global__ __launch_bounds__(256)
void prep_w(const float* __restrict__ W) {
    __shared__ float tile[32][33];
    const int tx = threadIdx.x, ty = threadIdx.y;     // (32, 8)
    const int n0 = blockIdx.x * 32, k0 = blockIdx.y * 32;
#pragma unroll
    for (int i = 0; i < 32; i += 8)
        tile[ty + i][tx] = W[(size_t)(k0 + ty + i) * HDIM + n0 + tx];
    __syncthreads();
#pragma unroll
    for (int i = 0; i < 32; i += 8) {
        const int n = n0 + ty + i, k = k0 + tx;
        float v = tile[tx][ty + i];
        __half h = __float2half_rn(v);
        float r = v - __half2float(h);
        g_Wt_hi[(size_t)n * HDIM + k] = h;
        g_Wt_lo[(size_t)n * HDIM + k] = __float2half_rn(r);
    }
}

// ===================== fused: A fp16 convert + sparse head =====================
// one warp per token: convert row to fp16 plane AND compute sparse dot,
// relu, scatter-max into the vocab grid. Special ids 0..3 filtered here.
__global__ __launch_bounds__(256)
void split_scatter(const float* __restrict__ hs, const int* __restrict__ idw,
                   const float* __restrict__ sw, const float* __restrict__ sb,
                   float* __restrict__ sp) {
    __shared__ float wsh[HDIM];
    const int t = threadIdx.x;
    ((float4*)wsh)[t] = ((const float4*)sw)[t];
    __syncthreads();

    const int lane = t & 31;
    const int wp   = t >> 5;

    // int64-vs-int32 layout detection (int64 ids < 2^31 have zero high words)
    const int odd = idw[2 * lane + 1];
    const bool is64 = __all_sync(0xFFFFFFFFu, odd == 0);

    const int tok = blockIdx.x * 8 + wp;
    const float* row = hs + (size_t)tok * HDIM;
    __half* ah = g_Ah + (size_t)tok * HDIM;

    float s = 0.f;
#pragma unroll
    for (int j = 0; j < 8; j++) {
        const int off = lane * 4 + j * 128;
        const float4 h  = *(const float4*)(row + off);
        const float4 ww = *(const float4*)(wsh + off);
        s += h.x * ww.x + h.y * ww.y + h.z * ww.z + h.w * ww.w;
        *(uint2*)(ah + off) = make_uint2(hpack(h.x, h.y), hpack(h.z, h.w));
    }
#pragma unroll
    for (int o = 16; o > 0; o >>= 1) s += __shfl_xor_sync(0xFFFFFFFFu, s, o);

    if (lane == 0) {
        const float val = s + sb[0];
        if (val > 0.f) {
            long long id = is64 ? ((const long long*)idw)[tok] : (long long)idw[tok];
            // ids 0..3 are the special tokens (cls/pad/eos/unk) -> stay zero
            if (id >= 4 && id < VOCAB) {
                const int b = tok >> 11;
                atomicMax((int*)&sp[(size_t)b * VOCAB + (int)id], __float_as_int(val));
            }
        }
    }
}

// ===================== colbert GEMM via mma.sync fp16 (2-product asym split) =====================
// C[m,n] = A[mrow(m),:] . W[:,n] + bias[n],  mrow(m) = m + m/2047 + 1
// A: single fp16; W: fp16 hi + fp16 lo.  C = Ah*Wh + Ah*Wl
#define BM 128
#define BN 128
#define BKC 32                       // fp16 k per chunk
#define NC  (HDIM / BKC)             // 32 chunks
#define STAGES 4
#define ROWB 80                      // padded smem row bytes (32 f16 data + 16B pad)
#define PLANE (BM * ROWB)            // 10240 B
#define STAGE (3 * PLANE)            // Ah, Bh, Bl = 30720 B
#define GEMM_SMEM (STAGES * STAGE)   // 122880 B

__global__ __launch_bounds__(256, 1)
void colbert_gemm_mma(const float* __restrict__ bias, float* __restrict__ C) {
    extern __shared__ char smem[];
    const uint32_t sb = smem_u32(smem);
    const int t = threadIdx.x, lane = t & 31, wid = t >> 5;
    const int m0 = blockIdx.y * BM;
    const int n0 = blockIdx.x * BN;

    // ---- load mapping (per thread): row lr = t>>1, 32B half lh = t&1 ----
    const int lr = t >> 1, lh = t & 1;
    const int am = m0 + lr;
    const int arow = (am < MROWS) ? (am + am / SM1 + 1) : 0;
    const __half* gah = g_Ah + (size_t)arow * HDIM + lh * 16;
    const __half* gbh = g_Wt_hi + (size_t)(n0 + lr) * HDIM + lh * 16;
    const __half* gbl = g_Wt_lo + (size_t)(n0 + lr) * HDIM + lh * 16;
    const uint32_t s_row = (uint32_t)lr * ROWB + (uint32_t)lh * 32;

    // ---- warp compute mapping: 4(m) x 2(n) warps; warp tile 32x64 ----
    const int wm = wid >> 1, wn = wid & 1;
    const uint32_t a_r  = (uint32_t)((lane & 7) + ((lane >> 3) & 1) * 8);
    const uint32_t a_kb = (uint32_t)((lane >> 4) * 16);
    const uint32_t b_r  = (uint32_t)((lane & 7) + ((lane >> 4) & 1) * 8);
    const uint32_t b_kb = (uint32_t)(((lane >> 3) & 1) * 16);

    float d[2][8][4];
#pragma unroll
    for (int i = 0; i < 2; i++)
#pragma unroll
        for (int j = 0; j < 8; j++)
#pragma unroll
            for (int q = 0; q < 4; q++) d[i][j][q] = 0.f;

    // ---- per-chunk load issue: Ah (1 plane) + Bh + Bl ----
#define ISSUE_LOADS(c) do {                                                  \
        const int _c = (c);                                                  \
        const uint32_t _sA = sb + (uint32_t)(_c & (STAGES - 1)) * STAGE + s_row; \
        const uint32_t _sB = _sA + PLANE;                                    \
        const __half* _ah = gah + _c * BKC;                                  \
        const __half* _bh = gbh + _c * BKC;                                  \
        const __half* _bl = gbl + _c * BKC;                                  \
        CP_ASYNC16(_sA,              _ah);                                   \
        CP_ASYNC16(_sA + 16,         _ah + 8);                               \
        CP_ASYNC16(_sB,              _bh);                                   \
        CP_ASYNC16(_sB + 16,         _bh + 8);                               \
        CP_ASYNC16(_sB + PLANE,      _bl);                                   \
        CP_ASYNC16(_sB + PLANE + 16, _bl + 8);                               \
    } while (0)

    // ---- prologue: fill STAGES-1 stages ----
#pragma unroll
    for (int c = 0; c < STAGES - 1; c++) {
        ISSUE_LOADS(c);
        CP_COMMIT();
    }

    // ---- main loop ----
    for (int c = 0; c < NC; c++) {
        CP_WAIT2();
        __syncthreads();

        if (c + STAGES - 1 < NC) ISSUE_LOADS(c + STAGES - 1);
        CP_COMMIT();

        const uint32_t st = sb + (uint32_t)(c & (STAGES - 1)) * STAGE;
        const uint32_t aA = st + (uint32_t)(wm * 32) * ROWB + a_r * ROWB + a_kb;
        const uint32_t aB = st + PLANE + (uint32_t)(wn * 64) * ROWB + b_r * ROWB + b_kb;
#pragma unroll
        for (int k16 = 0; k16 < 2; k16++) {
            const uint32_t ko = (uint32_t)(k16 * 32);
            unsigned ah[2][4], bh[4][4], bl[4][4];
#pragma unroll
            for (int mt = 0; mt < 2; mt++)
                LDSM4(ah[mt], aA + (uint32_t)(mt * 16) * ROWB + ko);
#pragma unroll
            for (int p = 0; p < 4; p++) {
                LDSM4(bh[p], aB + (uint32_t)(p * 16) * ROWB + ko);
                LDSM4(bl[p], aB + (uint32_t)(p * 16) * ROWB + ko + PLANE);
            }
            // term 1: a * w_hi
#pragma unroll
            for (int mt = 0; mt < 2; mt++)
#pragma unroll
                for (int p = 0; p < 4; p++) {
                    MMA16816(d[mt][2 * p],     ah[mt], bh[p][0], bh[p][1]);
                    MMA16816(d[mt][2 * p + 1], ah[mt], bh[p][2], bh[p][3]);
                }
            // term 2: a * w_lo
#pragma unroll
            for (int mt = 0; mt < 2; mt++)
#pragma unroll
                for (int p = 0; p < 4; p++) {
                    MMA16816(d[mt][2 * p],     ah[mt], bl[p][0], bl[p][1]);
                    MMA16816(d[mt][2 * p + 1], ah[mt], bl[p][2], bl[p][3]);
                }
        }
    }
#undef ISSUE_LOADS

    // ---------------- epilogue ----------------
    {
        const int row = lane >> 2, col2 = (lane & 3) * 2;
        const int nb = n0 + wn * 64;
#pragma unroll
        for (int nt = 0; nt < 8; nt++) {
            const int n = nb + nt * 8 + col2;
            const float b0 = __ldg(bias + n);
            const float b1 = __ldg(bias + n + 1);
#pragma unroll
            for (int mt = 0; mt < 2; mt++) {
                const int m = m0 + wm * 32 + mt * 16 + row;
                if (m < MROWS)
                    *(float2*)(C + (size_t)m * HDIM + n) =
                        make_float2(d[mt][nt][0] + b0, d[mt][nt][1] + b1);
                if (m + 8 < MROWS)
                    *(float2*)(C + (size_t)(m + 8) * HDIM + n) =
                        make_float2(d[mt][nt][2] + b0, d[mt][nt][3] + b1);
            }
        }
    }
}

// ===================== mask + L2 normalize colbert rows =====================
__global__ __launch_bounds__(256)
void colbert_norm(float* __restrict__ C, const float* __restrict__ mask) {
    const int r = blockIdx.x;
    const int b = r / SM1;
    const int s = r - b * SM1 + 1;
    const float mk = mask[b * SEQ + s];
    float4* row = (float4*)(C + (size_t)r * HDIM);
    const int t = threadIdx.x;
    float4 v = row[t];
    v.x *= mk; v.y *= mk; v.z *= mk; v.w *= mk;
    float ss = v.x * v.x + v.y * v.y + v.z * v.z + v.w * v.w;
#pragma unroll
    for (int o = 16; o > 0; o >>= 1) ss += __shfl_xor_sync(0xFFFFFFFFu, ss, o);
    __shared__ float ws[8];
    __shared__ float sscale;
    if ((t & 31) == 0) ws[t >> 5] = ss;
    __syncthreads();
    if (t == 0) {
        float tot = 0.f;
#pragma unroll
        for (int i = 0; i < 8; i++) tot += ws[i];
        sscale = 1.f / fmaxf(sqrtf(tot), EPSN);
    }
    __syncthreads();
    const float sc = sscale;
    v.x *= sc; v.y *= sc; v.z *= sc; v.w *= sc;
    row[t] = v;
}

// ===================== dense head =====================
__global__ __launch_bounds__(256)
void dense_norm(const float* __restrict__ hs, float* __restrict__ o) {
    const int b = blockIdx.x;
    const int t = threadIdx.x;
    const float4* row = (const float4*)(hs + (size_t)b * SEQ * HDIM);
    float4 v = row[t];
    float ss = v.x * v.x + v.y * v.y + v.z * v.z + v.w * v.w;
#pragma unroll
    for (int o2 = 16; o2 > 0; o2 >>= 1) ss += __shfl_xor_sync(0xFFFFFFFFu, ss, o2);
    __shared__ float ws[8];
    __shared__ float sscale;
    if ((t & 31) == 0) ws[t >> 5] = ss;
    __syncthreads();
    if (t == 0) {
        float tot = 0.f;
#pragma unroll
        for (int i = 0; i < 8; i++) tot += ws[i];
        sscale = 1.f / fmaxf(sqrtf(tot), EPSN);
    }
    __syncthreads();
    const float sc = sscale;
    v.x *= sc; v.y *= sc; v.z *= sc; v.w *= sc;
    ((float4*)(o + (size_t)b * HDIM))[t] = v;
}

// ===================== sparse zero =====================
__global__ __launch_bounds__(512)
void sparse_zero(float4* __restrict__ p) {
    const int n = (BATCH * VOCAB) / 4;  // exact
    const float4 z = make_float4(0.f, 0.f, 0.f, 0.f);
    for (int i = blockIdx.x * blockDim.x + threadIdx.x; i < n; i += gridDim.x * blockDim.x)
        p[i] = z;
}

// ===================== launch =====================
extern "C" void kernel_launch(void* const* d_in, const int* in_sizes, int n_in,
                              void* d_out, int out_size) {
    const float* hs   = (const float*)d_in[0];
    const float* mask = (const float*)d_in[1];
    const int*   ids  = (const int*)d_in[2];
    const float* sW   = (const float*)d_in[3];
    const float* sbp  = (const float*)d_in[4];
    const float* cW   = (const float*)d_in[5];
    const float* cb   = (const float*)d_in[6];

    float* out      = (float*)d_out;
    float* o_dense  = out;
    float* o_sparse = out + (size_t)BATCH * HDIM;
    float* o_col    = o_sparse + (size_t)BATCH * VOCAB;

    cudaFuncSetAttribute(colbert_gemm_mma, cudaFuncAttributeMaxDynamicSharedMemorySize, GEMM_SMEM);

    dense_norm<<<BATCH, 256>>>(hs, o_dense);
    sparse_zero<<<2048, 512>>>((float4*)o_sparse);
    prep_w<<<dim3(32, 32), dim3(32, 8)>>>(cW);
    split_scatter<<<NTOK / 8, 256>>>(hs, ids, sW, sbp, o_sparse);

    dim3 grid(HDIM / BN, (MROWS + BM - 1) / BM);   // (8, 256)
    colbert_gemm_mma<<<grid, 256, GEMM_SMEM>>>(cb, o_col);

    colbert_norm<<<MROWS, 256>>>(o_col, mask);
}

// round 14
// speedup vs baseline: 4.6462x; 1.7154x over previous
#include <cuda_runtime.h>
#include <cuda_fp16.h>
#include <cstdint>

#define VOCAB   250002
#define BATCH   16
#define SEQ     2048
#define HDIM    1024
#define SM1     2047               // SEQ-1
#define MROWS   (BATCH * SM1)      // 32752
#define NTOK    (BATCH * SEQ)      // 32768
#define EPSN    1e-12f

// ===================== small helpers =====================
static __device__ __forceinline__ uint32_t smem_u32(const void* p) {
    uint32_t a;
    asm("{ .reg .u64 t; cvta.to.shared.u64 t, %1; cvt.u32.u64 %0, t; }" : "=r"(a) : "l"(p));
    return a;
}
// pack two floats to f16x2 (first arg -> low half)
static __device__ __forceinline__ unsigned hpack(float lo, float hi) {
    unsigned r;
    asm("cvt.rn.f16x2.f32 %0, %1, %2;" : "=r"(r) : "f"(hi), "f"(lo));
    return r;
}

#define CP_ASYNC16(s, g) \
    asm volatile("cp.async.cg.shared.global [%0], [%1], 16;" :: "r"(s), "l"(g))
#define CP_COMMIT()  asm volatile("cp.async.commit_group;" ::: "memory")
#define CP_WAIT2()   asm volatile("cp.async.wait_group 2;" ::: "memory")

#define LDSM4(R, a) \
    asm volatile("ldmatrix.sync.aligned.m8n8.x4.shared.b16 {%0,%1,%2,%3}, [%4];" \
        : "=r"((R)[0]), "=r"((R)[1]), "=r"((R)[2]), "=r"((R)[3]) : "r"(a))

#define MMA16816(D, A, B0, B1) \
    asm volatile("mma.sync.aligned.m16n8k16.row.col.f32.f16.f16.f32 " \
        "{%0,%1,%2,%3}, {%4,%5,%6,%7}, {%8,%9}, {%0,%1,%2,%3};" \
        : "+f"((D)[0]), "+f"((D)[1]), "+f"((D)[2]), "+f"((D)[3]) \
        : "r"((A)[0]), "r"((A)[1]), "r"((A)[2]), "r"((A)[3]), "r"(B0), "r"(B1))

// ===================== device scratch =====================
__device__ __half g_Wt[HDIM * HDIM];               // [N, K] K-contig, fp16
__device__ __half g_Ah[(size_t)NTOK * HDIM];       // hidden fp16, token order

// ===================== W pre-transpose, fp16 =====================
__global__ __launch_bounds__(256)
void prep_w(const float* __restrict__ W) {
    __shared__ float tile[32][33];
    const int tx = threadIdx.x, ty = threadIdx.y;     // (32, 8)
    const int n0 = blockIdx.x * 32, k0 = blockIdx.y * 32;
#pragma unroll
    for (int i = 0; i < 32; i += 8)
        tile[ty + i][tx] = W[(size_t)(k0 + ty + i) * HDIM + n0 + tx];
    __syncthreads();
#pragma unroll
    for (int i = 0; i < 32; i += 8) {
        const int n = n0 + ty + i, k = k0 + tx;
        g_Wt[(size_t)n * HDIM + k] = __float2half_rn(tile[tx][ty + i]);
    }
}

// ===================== fused: A fp16 convert + sparse head =====================
__global__ __launch_bounds__(256)
void split_scatter(const float* __restrict__ hs, const int* __restrict__ idw,
                   const float* __restrict__ sw, const float* __restrict__ sb,
                   float* __restrict__ sp) {
    __shared__ float wsh[HDIM];
    const int t = threadIdx.x;
    ((float4*)wsh)[t] = ((const float4*)sw)[t];
    __syncthreads();

    const int lane = t & 31;
    const int wp   = t >> 5;

    // int64-vs-int32 layout detection (int64 ids < 2^31 have zero high words)
    const int odd = idw[2 * lane + 1];
    const bool is64 = __all_sync(0xFFFFFFFFu, odd == 0);

    const int tok = blockIdx.x * 8 + wp;
    const float* row = hs + (size_t)tok * HDIM;
    __half* ah = g_Ah + (size_t)tok * HDIM;

    float s = 0.f;
#pragma unroll
    for (int j = 0; j < 8; j++) {
        const int off = lane * 4 + j * 128;
        const float4 h  = *(const float4*)(row + off);
        const float4 ww = *(const float4*)(wsh + off);
        s += h.x * ww.x + h.y * ww.y + h.z * ww.z + h.w * ww.w;
        *(uint2*)(ah + off) = make_uint2(hpack(h.x, h.y), hpack(h.z, h.w));
    }
#pragma unroll
    for (int o = 16; o > 0; o >>= 1) s += __shfl_xor_sync(0xFFFFFFFFu, s, o);

    if (lane == 0) {
        const float val = s + sb[0];
        if (val > 0.f) {
            long long id = is64 ? ((const long long*)idw)[tok] : (long long)idw[tok];
            // ids 0..3 are the special tokens (cls/pad/eos/unk) -> stay zero
            if (id >= 4 && id < VOCAB) {
                const int b = tok >> 11;
                atomicMax((int*)&sp[(size_t)b * VOCAB + (int)id], __float_as_int(val));
            }
        }
    }
}

// ===================== colbert GEMM via mma.sync fp16 (single pass) =====================
// C[m,n] = A[mrow(m),:] . W[:,n] + bias[n],  mrow(m) = m + m/2047 + 1
#define BM 128
#define BN 128
#define BKC 32                       // fp16 k per chunk
#define NC  (HDIM / BKC)             // 32 chunks
#define STAGES 4
#define ROWB 80                      // padded smem row bytes (32 f16 data + 16B pad)
#define PLANE (BM * ROWB)            // 10240 B
#define STAGE (2 * PLANE)            // A, B = 20480 B
#define GEMM_SMEM (STAGES * STAGE)   // 81920 B

__global__ __launch_bounds__(256, 2)
void colbert_gemm_mma(const float* __restrict__ bias, float* __restrict__ C) {
    extern __shared__ char smem[];
    const uint32_t sb = smem_u32(smem);
    const int t = threadIdx.x, lane = t & 31, wid = t >> 5;
    const int m0 = blockIdx.y * BM;
    const int n0 = blockIdx.x * BN;

    // ---- load mapping (per thread): row lr = t>>1, 32B half lh = t&1 ----
    const int lr = t >> 1, lh = t & 1;
    const int am = m0 + lr;
    const int arow = (am < MROWS) ? (am + am / SM1 + 1) : 0;
    const __half* gah = g_Ah + (size_t)arow * HDIM + lh * 16;
    const __half* gbh = g_Wt + (size_t)(n0 + lr) * HDIM + lh * 16;
    const uint32_t s_row = (uint32_t)lr * ROWB + (uint32_t)lh * 32;

    // ---- warp compute mapping: 4(m) x 2(n) warps; warp tile 32x64 ----
    const int wm = wid >> 1, wn = wid & 1;
    const uint32_t a_r  = (uint32_t)((lane & 7) + ((lane >> 3) & 1) * 8);
    const uint32_t a_kb = (uint32_t)((lane >> 4) * 16);
    const uint32_t b_r  = (uint32_t)((lane & 7) + ((lane >> 4) & 1) * 8);
    const uint32_t b_kb = (uint32_t)(((lane >> 3) & 1) * 16);

    float d[2][8][4];
#pragma unroll
    for (int i = 0; i < 2; i++)
#pragma unroll
        for (int j = 0; j < 8; j++)
#pragma unroll
            for (int q = 0; q < 4; q++) d[i][j][q] = 0.f;

    // ---- per-chunk load issue: A + B (one plane each) ----
#define ISSUE_LOADS(c) do {                                                  \
        const int _c = (c);                                                  \
        const uint32_t _sA = sb + (uint32_t)(_c & (STAGES - 1)) * STAGE + s_row; \
        const uint32_t _sB = _sA + PLANE;                                    \
        const __half* _ah = gah + _c * BKC;                                  \
        const __half* _bh = gbh + _c * BKC;                                  \
        CP_ASYNC16(_sA,      _ah);                                           \
        CP_ASYNC16(_sA + 16, _ah + 8);                                       \
        CP_ASYNC16(_sB,      _bh);                                           \
        CP_ASYNC16(_sB + 16, _bh + 8);                                       \
    } while (0)

    // ---- prologue: fill STAGES-1 stages ----
#pragma unroll
    for (int c = 0; c < STAGES - 1; c++) {
        ISSUE_LOADS(c);
        CP_COMMIT();
    }

    // ---- main loop ----
    for (int c = 0; c < NC; c++) {
        CP_WAIT2();
        __syncthreads();

        if (c + STAGES - 1 < NC) ISSUE_LOADS(c + STAGES - 1);
        CP_COMMIT();

        const uint32_t st = sb + (uint32_t)(c & (STAGES - 1)) * STAGE;
        const uint32_t aA = st + (uint32_t)(wm * 32) * ROWB + a_r * ROWB + a_kb;
        const uint32_t aB = st + PLANE + (uint32_t)(wn * 64) * ROWB + b_r * ROWB + b_kb;
#pragma unroll
        for (int k16 = 0; k16 < 2; k16++) {
            const uint32_t ko = (uint32_t)(k16 * 32);
            unsigned ah[2][4], bh[4][4];
#pragma unroll
            for (int mt = 0; mt < 2; mt++)
                LDSM4(ah[mt], aA + (uint32_t)(mt * 16) * ROWB + ko);
#pragma unroll
            for (int p = 0; p < 4; p++)
                LDSM4(bh[p], aB + (uint32_t)(p * 16) * ROWB + ko);
#pragma unroll
            for (int mt = 0; mt < 2; mt++)
#pragma unroll
                for (int p = 0; p < 4; p++) {
                    MMA16816(d[mt][2 * p],     ah[mt], bh[p][0], bh[p][1]);
                    MMA16816(d[mt][2 * p + 1], ah[mt], bh[p][2], bh[p][3]);
                }
        }
    }
#undef ISSUE_LOADS

    // ---------------- epilogue ----------------
    {
        const int row = lane >> 2, col2 = (lane & 3) * 2;
        const int nb = n0 + wn * 64;
#pragma unroll
        for (int nt = 0; nt < 8; nt++) {
            const int n = nb + nt * 8 + col2;
            const float b0 = __ldg(bias + n);
            const float b1 = __ldg(bias + n + 1);
#pragma unroll
            for (int mt = 0; mt < 2; mt++) {
                const int m = m0 + wm * 32 + mt * 16 + row;
                if (m < MROWS)
                    *(float2*)(C + (size_t)m * HDIM + n) =
                        make_float2(d[mt][nt][0] + b0, d[mt][nt][1] + b1);
                if (m + 8 < MROWS)
                    *(float2*)(C + (size_t)(m + 8) * HDIM + n) =
                        make_float2(d[mt][nt][2] + b0, d[mt][nt][3] + b1);
            }
        }
    }
}

// ===================== mask + L2 normalize colbert rows =====================
__global__ __launch_bounds__(256)
void colbert_norm(float* __restrict__ C, const float* __restrict__ mask) {
    const int r = blockIdx.x;
    const int b = r / SM1;
    const int s = r - b * SM1 + 1;
    const float mk = mask[b * SEQ + s];
    float4* row = (float4*)(C + (size_t)r * HDIM);
    const int t = threadIdx.x;
    float4 v = row[t];
    v.x *= mk; v.y *= mk; v.z *= mk; v.w *= mk;
    float ss = v.x * v.x + v.y * v.y + v.z * v.z + v.w * v.w;
#pragma unroll
    for (int o = 16; o > 0; o >>= 1) ss += __shfl_xor_sync(0xFFFFFFFFu, ss, o);
    __shared__ float ws[8];
    __shared__ float sscale;
    if ((t & 31) == 0) ws[t >> 5] = ss;
    __syncthreads();
    if (t == 0) {
        float tot = 0.f;
#pragma unroll
        for (int i = 0; i < 8; i++) tot += ws[i];
        sscale = 1.f / fmaxf(sqrtf(tot), EPSN);
    }
    __syncthreads();
    const float sc = sscale;
    v.x *= sc; v.y *= sc; v.z *= sc; v.w *= sc;
    row[t] = v;
}

// ===================== dense head =====================
__global__ __launch_bounds__(256)
void dense_norm(const float* __restrict__ hs, float* __restrict__ o) {
    const int b = blockIdx.x;
    const int t = threadIdx.x;
    const float4* row = (const float4*)(hs + (size_t)b * SEQ * HDIM);
    float4 v = row[t];
    float ss = v.x * v.x + v.y * v.y + v.z * v.z + v.w * v.w;
#pragma unroll
    for (int o2 = 16; o2 > 0; o2 >>= 1) ss += __shfl_xor_sync(0xFFFFFFFFu, ss, o2);
    __shared__ float ws[8];
    __shared__ float sscale;
    if ((t & 31) == 0) ws[t >> 5] = ss;
    __syncthreads();
    if (t == 0) {
        float tot = 0.f;
#pragma unroll
        for (int i = 0; i < 8; i++) tot += ws[i];
        sscale = 1.f / fmaxf(sqrtf(tot), EPSN);
    }
    __syncthreads();
    const float sc = sscale;
    v.x *= sc; v.y *= sc; v.z *= sc; v.w *= sc;
    ((float4*)(o + (size_t)b * HDIM))[t] = v;
}

// ===================== sparse zero =====================
__global__ __launch_bounds__(512)
void sparse_zero(float4* __restrict__ p) {
    const int n = (BATCH * VOCAB) / 4;  // exact
    const float4 z = make_float4(0.f, 0.f, 0.f, 0.f);
    for (int i = blockIdx.x * blockDim.x + threadIdx.x; i < n; i += gridDim.x * blockDim.x)
        p[i] = z;
}

// ===================== launch =====================
extern "C" void kernel_launch(void* const* d_in, const int* in_sizes, int n_in,
                              void* d_out, int out_size) {
    const float* hs   = (const float*)d_in[0];
    const float* mask = (const float*)d_in[1];
    const int*   ids  = (const int*)d_in[2];
    const float* sW   = (const float*)d_in[3];
    const float* sbp  = (const float*)d_in[4];
    const float* cW   = (const float*)d_in[5];
    const float* cb   = (const float*)d_in[6];

    float* out      = (float*)d_out;
    float* o_dense  = out;
    float* o_sparse = out + (size_t)BATCH * HDIM;
    float* o_col    = o_sparse + (size_t)BATCH * VOCAB;

    cudaFuncSetAttribute(colbert_gemm_mma, cudaFuncAttributeMaxDynamicSharedMemorySize, GEMM_SMEM);

    dense_norm<<<BATCH, 256>>>(hs, o_dense);
    sparse_zero<<<2048, 512>>>((float4*)o_sparse);
    prep_w<<<dim3(32, 32), dim3(32, 8)>>>(cW);
    split_scatter<<<NTOK / 8, 256>>>(hs, ids, sW, sbp, o_sparse);

    dim3 grid(HDIM / BN, (MROWS + BM - 1) / BM);   // (8, 256)
    colbert_gemm_mma<<<grid, 256, GEMM_SMEM>>>(cb, o_col);

    colbert_norm<<<MROWS, 256>>>(o_col, mask);
}